// round 5
// baseline (speedup 1.0000x reference)
#include <cuda_runtime.h>
#include <cuda_bf16.h>
#include <stdint.h>

namespace {

constexpr int Bb = 4, Ss = 2048, Hh = 16, Dd = 64;
constexpr int BM = 64, BN = 64;
constexpr int KPAD = 72;   // u32 stride, sQ/sK paired layout: 8B-bank = 36g+4ks+c distinct mod 32
constexpr int VPAD = 144;  // u32 stride, sV hi/lo interleaved: 8B-bank = 8c+g distinct mod 32
constexpr float SCALE = 0.125f;
constexpr float NEGINF = -1e30f;

// u32 offsets in dynamic smem
constexpr int OQ = 0;                 // 64 * 72 = 4608
constexpr int OK = 4608;              // 64 * 72 = 4608
constexpr int OV = 9216;              // 32 * 144 = 4608
constexpr int SMEM_BYTES = (9216 + 4608) * 4;   // 55296

__device__ __forceinline__ uint32_t f2tf32(float f) {
    uint32_t r;
    asm("cvt.rna.tf32.f32 %0, %1;" : "=r"(r) : "f"(f));
    return r;
}
__device__ __forceinline__ uint32_t packbf2(float lo, float hi) {
    uint32_t r;
    asm("cvt.rn.bf16x2.f32 %0, %1, %2;" : "=r"(r) : "f"(hi), "f"(lo));
    return r;
}
__device__ __forceinline__ float lo16f(uint32_t u) { return __uint_as_float(u << 16); }
__device__ __forceinline__ float hi16f(uint32_t u) { return __uint_as_float(u & 0xffff0000u); }

// column permutation for paired fragment loads: d -> ks*8 + (d&3)*2 + ((d>>2)&1)
__device__ __forceinline__ int kperm(int d) {
    return (d & ~7) + ((d & 3) << 1) + ((d >> 2) & 1);
}

__device__ __forceinline__ void mma_tf32(float c[4], const uint32_t a[4], const uint32_t b[2]) {
    asm volatile(
        "mma.sync.aligned.m16n8k8.row.col.f32.tf32.tf32.f32 "
        "{%0,%1,%2,%3}, {%4,%5,%6,%7}, {%8,%9}, {%0,%1,%2,%3};"
        : "+f"(c[0]), "+f"(c[1]), "+f"(c[2]), "+f"(c[3])
        : "r"(a[0]), "r"(a[1]), "r"(a[2]), "r"(a[3]), "r"(b[0]), "r"(b[1]));
}
__device__ __forceinline__ void mma_bf16(float c[4], const uint32_t a[4], const uint32_t b[2]) {
    asm volatile(
        "mma.sync.aligned.m16n8k16.row.col.f32.bf16.bf16.f32 "
        "{%0,%1,%2,%3}, {%4,%5,%6,%7}, {%8,%9}, {%0,%1,%2,%3};"
        : "+f"(c[0]), "+f"(c[1]), "+f"(c[2]), "+f"(c[3])
        : "r"(a[0]), "r"(a[1]), "r"(a[2]), "r"(a[3]), "r"(b[0]), "r"(b[1]));
}

__global__ void __launch_bounds__(128, 3)
fa_kernel(const float* __restrict__ q, const float* __restrict__ k,
          const float* __restrict__ v, const float* __restrict__ bias,
          float* __restrict__ out)
{
    extern __shared__ __align__(16) uint32_t smem[];
    uint32_t* sQ = smem + OQ;   // [64][72] tf32, perm cols
    uint32_t* sK = smem + OK;   // [64][72] tf32, perm cols
    uint32_t* sV = smem + OV;   // [32][144] bf16x2 row-pairs, hi/lo interleaved

    const int tid  = threadIdx.x;
    const int lane = tid & 31;
    const int wid  = tid >> 5;
    const int g    = lane >> 2;
    const int c    = lane & 3;

    // grid: batch fastest-varying (bias L2 reuse); qt reversed (longest first)
    const int idx = blockIdx.x;
    const int b   = idx & 3;
    const int h   = (idx >> 2) & 15;
    const int qt  = (Ss / BM - 1) - (idx >> 6);
    const int qrow = qt * BM;

    const int r0 = qrow + wid * 16 + g;
    const int r1 = r0 + 8;

    // ---- Q tile -> smem (tf32, perm layout), once ----
    {
        const float* qb = q + ((size_t)(b * Ss + qrow) * Hh + h) * Dd;
#pragma unroll
        for (int it = 0; it < 8; it++) {
            const int t  = it * 128 + tid;
            const int n  = t >> 4;
            const int d4 = (t & 15) << 2;
            const float4 f = *(const float4*)(qb + (size_t)n * (Hh * Dd) + d4);
            uint32_t* row = &sQ[n * KPAD];
            row[kperm(d4 + 0)] = f2tf32(f.x);
            row[kperm(d4 + 1)] = f2tf32(f.y);
            row[kperm(d4 + 2)] = f2tf32(f.z);
            row[kperm(d4 + 3)] = f2tf32(f.w);
        }
    }

    float oacc[8][4];
#pragma unroll
    for (int i = 0; i < 8; i++) {
        oacc[i][0] = 0.f; oacc[i][1] = 0.f; oacc[i][2] = 0.f; oacc[i][3] = 0.f;
    }
    float m0 = NEGINF, m1 = NEGINF, l0 = 0.f, l1 = 0.f;

    const float* biasr0 = bias + ((size_t)h * Ss + r0) * Ss;
    const float* biasr1 = bias + ((size_t)h * Ss + r1) * Ss;

    const int qrow_loc = wid * 16 + g;   // local q row for fragment loads

    for (int j = 0; j <= qt; j++) {
        __syncthreads();
        const size_t base = ((size_t)(b * Ss + j * BN) * Hh + h) * Dd;

        // ---- K tile: fp32 -> tf32, perm layout ----
#pragma unroll
        for (int it = 0; it < 8; it++) {
            const int t  = it * 128 + tid;
            const int n  = t >> 4;
            const int d4 = (t & 15) << 2;
            const float4 f = *(const float4*)(k + base + (size_t)n * (Hh * Dd) + d4);
            uint32_t* row = &sK[n * KPAD];
            row[kperm(d4 + 0)] = f2tf32(f.x);
            row[kperm(d4 + 1)] = f2tf32(f.y);
            row[kperm(d4 + 2)] = f2tf32(f.z);
            row[kperm(d4 + 3)] = f2tf32(f.w);
        }
        // ---- V tile: fp32 row-pairs -> bf16x2 hi/lo interleaved ----
#pragma unroll
        for (int it = 0; it < 4; it++) {
            const int t  = it * 128 + tid;
            const int rp = t >> 4;
            const int d4 = (t & 15) << 2;
            const float* vb = v + base + (size_t)(2 * rp) * (Hh * Dd) + d4;
            const float4 v0 = *(const float4*)(vb);
            const float4 v1 = *(const float4*)(vb + Hh * Dd);
            uint32_t hx = packbf2(v0.x, v1.x), hy = packbf2(v0.y, v1.y);
            uint32_t hz = packbf2(v0.z, v1.z), hw = packbf2(v0.w, v1.w);
            uint4 s0, s1;
            s0.x = hx; s0.y = packbf2(v0.x - lo16f(hx), v1.x - hi16f(hx));
            s0.z = hy; s0.w = packbf2(v0.y - lo16f(hy), v1.y - hi16f(hy));
            s1.x = hz; s1.y = packbf2(v0.z - lo16f(hz), v1.z - hi16f(hz));
            s1.z = hw; s1.w = packbf2(v0.w - lo16f(hw), v1.w - hi16f(hw));
            *(uint4*)(&sV[rp * VPAD + 2 * d4])     = s0;
            *(uint4*)(&sV[rp * VPAD + 2 * d4 + 4]) = s1;
        }
        __syncthreads();

        // ---- S = Q K^T (tf32 mma, fragments via LDS.64, ks-outer) ----
        float sacc[8][4];
#pragma unroll
        for (int nf = 0; nf < 8; nf++) {
            sacc[nf][0] = 0.f; sacc[nf][1] = 0.f; sacc[nf][2] = 0.f; sacc[nf][3] = 0.f;
        }
#pragma unroll
        for (int ks = 0; ks < 8; ks++) {
            const int qcol = ks * 8 + 2 * c;   // paired (d, d+4)
            const uint2 qf0 = *(const uint2*)&sQ[qrow_loc * KPAD + qcol];
            const uint2 qf1 = *(const uint2*)&sQ[(qrow_loc + 8) * KPAD + qcol];
            uint32_t af[4];
            af[0] = qf0.x; af[1] = qf1.x; af[2] = qf0.y; af[3] = qf1.y;
#pragma unroll
            for (int nf = 0; nf < 8; nf++) {
                const uint2 bf = *(const uint2*)&sK[(nf * 8 + g) * KPAD + qcol];
                uint32_t bfr[2];
                bfr[0] = bf.x; bfr[1] = bf.y;
                mma_tf32(sacc[nf], af, bfr);
            }
        }

        // ---- scale + bias + causal mask ----
        const int kcb = j * BN;
        const bool diag = (j == qt);
#pragma unroll
        for (int nf = 0; nf < 8; nf++) {
            const int kc = kcb + nf * 8 + 2 * c;
            const float2 bb0 = __ldg((const float2*)(biasr0 + kc));
            const float2 bb1 = __ldg((const float2*)(biasr1 + kc));
            sacc[nf][0] = sacc[nf][0] * SCALE + bb0.x;
            sacc[nf][1] = sacc[nf][1] * SCALE + bb0.y;
            sacc[nf][2] = sacc[nf][2] * SCALE + bb1.x;
            sacc[nf][3] = sacc[nf][3] * SCALE + bb1.y;
            if (diag) {
                if (kc     > r0) sacc[nf][0] = NEGINF;
                if (kc + 1 > r0) sacc[nf][1] = NEGINF;
                if (kc     > r1) sacc[nf][2] = NEGINF;
                if (kc + 1 > r1) sacc[nf][3] = NEGINF;
            }
        }

        // ---- online softmax ----
        float rm0 = NEGINF, rm1 = NEGINF;
#pragma unroll
        for (int nf = 0; nf < 8; nf++) {
            rm0 = fmaxf(rm0, fmaxf(sacc[nf][0], sacc[nf][1]));
            rm1 = fmaxf(rm1, fmaxf(sacc[nf][2], sacc[nf][3]));
        }
        rm0 = fmaxf(rm0, __shfl_xor_sync(0xffffffffu, rm0, 1));
        rm0 = fmaxf(rm0, __shfl_xor_sync(0xffffffffu, rm0, 2));
        rm1 = fmaxf(rm1, __shfl_xor_sync(0xffffffffu, rm1, 1));
        rm1 = fmaxf(rm1, __shfl_xor_sync(0xffffffffu, rm1, 2));

        const float nm0 = fmaxf(m0, rm0), nm1 = fmaxf(m1, rm1);
        const float a0 = __expf(m0 - nm0), a1 = __expf(m1 - nm1);
        m0 = nm0; m1 = nm1;

        float rs0 = 0.f, rs1 = 0.f;
#pragma unroll
        for (int nf = 0; nf < 8; nf++) {
            sacc[nf][0] = __expf(sacc[nf][0] - nm0);
            sacc[nf][1] = __expf(sacc[nf][1] - nm0);
            sacc[nf][2] = __expf(sacc[nf][2] - nm1);
            sacc[nf][3] = __expf(sacc[nf][3] - nm1);
            rs0 += sacc[nf][0] + sacc[nf][1];
            rs1 += sacc[nf][2] + sacc[nf][3];
        }
        l0 = l0 * a0 + rs0;
        l1 = l1 * a1 + rs1;

#pragma unroll
        for (int df = 0; df < 8; df++) {
            oacc[df][0] *= a0; oacc[df][1] *= a0;
            oacc[df][2] *= a1; oacc[df][3] *= a1;
        }

        // ---- O += P V (split-bf16; V hi/lo via one LDS.64 each) ----
#pragma unroll
        for (int t = 0; t < 4; t++) {
            uint32_t ahi[4], alo[4];
            {
                const float p00 = sacc[2 * t][0],     p01 = sacc[2 * t][1];
                const float p10 = sacc[2 * t][2],     p11 = sacc[2 * t][3];
                const float p20 = sacc[2 * t + 1][0], p21 = sacc[2 * t + 1][1];
                const float p30 = sacc[2 * t + 1][2], p31 = sacc[2 * t + 1][3];
                ahi[0] = packbf2(p00, p01);
                ahi[1] = packbf2(p10, p11);
                ahi[2] = packbf2(p20, p21);
                ahi[3] = packbf2(p30, p31);
                alo[0] = packbf2(p00 - lo16f(ahi[0]), p01 - hi16f(ahi[0]));
                alo[1] = packbf2(p10 - lo16f(ahi[1]), p11 - hi16f(ahi[1]));
                alo[2] = packbf2(p20 - lo16f(ahi[2]), p21 - hi16f(ahi[2]));
                alo[3] = packbf2(p30 - lo16f(ahi[3]), p31 - hi16f(ahi[3]));
            }
            const int rpb = t * 8 + c;
#pragma unroll
            for (int df = 0; df < 8; df++) {
                const uint2 v0 = *(const uint2*)&sV[rpb * VPAD + df * 16 + 2 * g];
                const uint2 v1 = *(const uint2*)&sV[(rpb + 4) * VPAD + df * 16 + 2 * g];
                uint32_t bhi[2], blo[2];
                bhi[0] = v0.x; bhi[1] = v1.x;
                blo[0] = v0.y; blo[1] = v1.y;
                mma_bf16(oacc[df], ahi, bhi);
                mma_bf16(oacc[df], ahi, blo);
                mma_bf16(oacc[df], alo, bhi);
            }
        }
    }

    // ---- epilogue ----
    l0 += __shfl_xor_sync(0xffffffffu, l0, 1);
    l0 += __shfl_xor_sync(0xffffffffu, l0, 2);
    l1 += __shfl_xor_sync(0xffffffffu, l1, 1);
    l1 += __shfl_xor_sync(0xffffffffu, l1, 2);
    const float inv0 = 1.0f / l0;
    const float inv1 = 1.0f / l1;

    float* o0 = out + ((size_t)(b * Ss + r0) * Hh + h) * Dd;
    float* o1 = out + ((size_t)(b * Ss + r1) * Hh + h) * Dd;
#pragma unroll
    for (int df = 0; df < 8; df++) {
        const int dc = df * 8 + 2 * c;
        float2 w0, w1;
        w0.x = oacc[df][0] * inv0; w0.y = oacc[df][1] * inv0;
        w1.x = oacc[df][2] * inv1; w1.y = oacc[df][3] * inv1;
        *(float2*)(o0 + dc) = w0;
        *(float2*)(o1 + dc) = w1;
    }
}

} // namespace

extern "C" void kernel_launch(void* const* d_in, const int* in_sizes, int n_in,
                              void* d_out, int out_size)
{
    const float* q    = (const float*)d_in[0];
    const float* k    = (const float*)d_in[1];
    const float* v    = (const float*)d_in[2];
    const float* bias = (const float*)d_in[3];
    float* out        = (float*)d_out;

    cudaFuncSetAttribute(fa_kernel, cudaFuncAttributeMaxDynamicSharedMemorySize, SMEM_BYTES);
    const dim3 grid(Bb * Hh * (Ss / BM));  // 2048 CTAs
    fa_kernel<<<grid, 128, SMEM_BYTES>>>(q, k, v, bias, out);
}

// round 6
// speedup vs baseline: 1.4883x; 1.4883x over previous
#include <cuda_runtime.h>
#include <cuda_bf16.h>
#include <stdint.h>

namespace {

constexpr int Bb = 4, Ss = 2048, Hh = 16, Dd = 64;
constexpr int BM = 64, BN = 64;
constexpr int PAD = 68;           // u32 per sK row: frag bank = 4g+c, conflict-free
constexpr int VP  = 72;           // u32 per sV row-pair: frag bank = 8c+g, conflict-free
constexpr float SCALE = 0.125f;   // 1/sqrt(64)
constexpr float NEGINF = -1e30f;

__device__ __forceinline__ uint32_t f2tf32(float f) {
    uint32_t r;
    asm("cvt.rna.tf32.f32 %0, %1;" : "=r"(r) : "f"(f));
    return r;
}
// pack two floats -> f16x2 (lower half = lo arg, upper half = hi arg)
__device__ __forceinline__ uint32_t packf16x2(float lo, float hi) {
    uint32_t r;
    asm("cvt.rn.f16x2.f32 %0, %1, %2;" : "=r"(r) : "f"(hi), "f"(lo));
    return r;
}

__device__ __forceinline__ void mma_tf32(float c[4], const uint32_t a[4], const uint32_t b[2]) {
    asm volatile(
        "mma.sync.aligned.m16n8k8.row.col.f32.tf32.tf32.f32 "
        "{%0,%1,%2,%3}, {%4,%5,%6,%7}, {%8,%9}, {%0,%1,%2,%3};"
        : "+f"(c[0]), "+f"(c[1]), "+f"(c[2]), "+f"(c[3])
        : "r"(a[0]), "r"(a[1]), "r"(a[2]), "r"(a[3]), "r"(b[0]), "r"(b[1]));
}
__device__ __forceinline__ void mma_f16(float c[4], const uint32_t a[4], const uint32_t b[2]) {
    asm volatile(
        "mma.sync.aligned.m16n8k16.row.col.f32.f16.f16.f32 "
        "{%0,%1,%2,%3}, {%4,%5,%6,%7}, {%8,%9}, {%0,%1,%2,%3};"
        : "+f"(c[0]), "+f"(c[1]), "+f"(c[2]), "+f"(c[3])
        : "r"(a[0]), "r"(a[1]), "r"(a[2]), "r"(a[3]), "r"(b[0]), "r"(b[1]));
}

__global__ void __launch_bounds__(128, 3)
fa_kernel(const float* __restrict__ q, const float* __restrict__ k,
          const float* __restrict__ v, const float* __restrict__ bias,
          float* __restrict__ out)
{
    __shared__ __align__(16) uint32_t sK[BN * PAD];      // K tile, tf32, [n][d]
    __shared__ __align__(16) uint32_t sV[(BN/2) * VP];   // V tile, f16x2 row pairs

    const int tid  = threadIdx.x;
    const int lane = tid & 31;
    const int wid  = tid >> 5;
    const int g    = lane >> 2;
    const int c    = lane & 3;

    // grid: batch fastest-varying (bias L2 reuse); qt reversed (longest first)
    const int idx = blockIdx.x;
    const int b   = idx & 3;
    const int h   = (idx >> 2) & 15;
    const int qt  = (Ss / BM - 1) - (idx >> 6);
    const int qrow = qt * BM;

    const int r0 = qrow + wid * 16 + g;
    const int r1 = r0 + 8;

    // ---- Q fragments (tf32), loaded once ----
    const float* q0 = q + ((size_t)(b * Ss + r0) * Hh + h) * Dd;
    const float* q1 = q + ((size_t)(b * Ss + r1) * Hh + h) * Dd;
    uint32_t qa[8][4];
#pragma unroll
    for (int ks = 0; ks < 8; ks++) {
        const int d0 = ks * 8 + c;
        qa[ks][0] = f2tf32(q0[d0]);
        qa[ks][1] = f2tf32(q1[d0]);
        qa[ks][2] = f2tf32(q0[d0 + 4]);
        qa[ks][3] = f2tf32(q1[d0 + 4]);
    }

    float oacc[8][4];
#pragma unroll
    for (int i = 0; i < 8; i++) {
        oacc[i][0] = 0.f; oacc[i][1] = 0.f; oacc[i][2] = 0.f; oacc[i][3] = 0.f;
    }
    float m0 = NEGINF, m1 = NEGINF, l0 = 0.f, l1 = 0.f;

    const float* biasr0 = bias + ((size_t)h * Ss + r0) * Ss;
    const float* biasr1 = bias + ((size_t)h * Ss + r1) * Ss;

    for (int j = 0; j <= qt; j++) {
        __syncthreads();
        const size_t base = ((size_t)(b * Ss + j * BN) * Hh + h) * Dd;

        // ---- K tile: fp32 -> tf32 once -> smem (clean uint4 stores) ----
#pragma unroll
        for (int it = 0; it < 8; it++) {
            const int t  = it * 128 + tid;
            const int n  = t >> 4;
            const int d4 = (t & 15) << 2;
            const float4 kv = *(const float4*)(k + base + (size_t)n * (Hh * Dd) + d4);
            uint4 kt;
            kt.x = f2tf32(kv.x); kt.y = f2tf32(kv.y);
            kt.z = f2tf32(kv.z); kt.w = f2tf32(kv.w);
            *(uint4*)(&sK[n * PAD + d4]) = kt;
        }
        // ---- V tile: fp32 row pairs -> f16x2 once -> smem ----
#pragma unroll
        for (int it = 0; it < 4; it++) {
            const int t  = it * 128 + tid;
            const int rp = t >> 4;
            const int d4 = (t & 15) << 2;
            const float* vb = v + base + (size_t)(2 * rp) * (Hh * Dd) + d4;
            const float4 v0 = *(const float4*)(vb);
            const float4 v1 = *(const float4*)(vb + Hh * Dd);
            uint4 hi;
            hi.x = packf16x2(v0.x, v1.x);
            hi.y = packf16x2(v0.y, v1.y);
            hi.z = packf16x2(v0.z, v1.z);
            hi.w = packf16x2(v0.w, v1.w);
            *(uint4*)(&sV[rp * VP + d4]) = hi;
        }
        __syncthreads();

        // ---- S = Q K^T (tf32 mma) ----
        float sacc[8][4];
#pragma unroll
        for (int nf = 0; nf < 8; nf++) {
            sacc[nf][0] = 0.f; sacc[nf][1] = 0.f; sacc[nf][2] = 0.f; sacc[nf][3] = 0.f;
#pragma unroll
            for (int ks = 0; ks < 8; ks++) {
                const uint32_t* kp = &sK[(nf * 8 + g) * PAD + ks * 8 + c];
                uint32_t bfr[2];
                bfr[0] = kp[0];
                bfr[1] = kp[4];
                mma_tf32(sacc[nf], qa[ks], bfr);
            }
        }

        // ---- scale + bias + causal mask ----
        const int kcb = j * BN;
        const bool diag = (j == qt);
#pragma unroll
        for (int nf = 0; nf < 8; nf++) {
            const int kc = kcb + nf * 8 + 2 * c;
            const float2 bb0 = __ldg((const float2*)(biasr0 + kc));
            const float2 bb1 = __ldg((const float2*)(biasr1 + kc));
            sacc[nf][0] = sacc[nf][0] * SCALE + bb0.x;
            sacc[nf][1] = sacc[nf][1] * SCALE + bb0.y;
            sacc[nf][2] = sacc[nf][2] * SCALE + bb1.x;
            sacc[nf][3] = sacc[nf][3] * SCALE + bb1.y;
            if (diag) {
                if (kc     > r0) sacc[nf][0] = NEGINF;
                if (kc + 1 > r0) sacc[nf][1] = NEGINF;
                if (kc     > r1) sacc[nf][2] = NEGINF;
                if (kc + 1 > r1) sacc[nf][3] = NEGINF;
            }
        }

        // ---- online softmax ----
        float rm0 = NEGINF, rm1 = NEGINF;
#pragma unroll
        for (int nf = 0; nf < 8; nf++) {
            rm0 = fmaxf(rm0, fmaxf(sacc[nf][0], sacc[nf][1]));
            rm1 = fmaxf(rm1, fmaxf(sacc[nf][2], sacc[nf][3]));
        }
        rm0 = fmaxf(rm0, __shfl_xor_sync(0xffffffffu, rm0, 1));
        rm0 = fmaxf(rm0, __shfl_xor_sync(0xffffffffu, rm0, 2));
        rm1 = fmaxf(rm1, __shfl_xor_sync(0xffffffffu, rm1, 1));
        rm1 = fmaxf(rm1, __shfl_xor_sync(0xffffffffu, rm1, 2));

        const float nm0 = fmaxf(m0, rm0), nm1 = fmaxf(m1, rm1);
        const float a0 = __expf(m0 - nm0), a1 = __expf(m1 - nm1);
        m0 = nm0; m1 = nm1;

        float rs0 = 0.f, rs1 = 0.f;
#pragma unroll
        for (int nf = 0; nf < 8; nf++) {
            sacc[nf][0] = __expf(sacc[nf][0] - nm0);
            sacc[nf][1] = __expf(sacc[nf][1] - nm0);
            sacc[nf][2] = __expf(sacc[nf][2] - nm1);
            sacc[nf][3] = __expf(sacc[nf][3] - nm1);
            rs0 += sacc[nf][0] + sacc[nf][1];
            rs1 += sacc[nf][2] + sacc[nf][3];
        }
        l0 = l0 * a0 + rs0;   // quad reduction deferred to epilogue
        l1 = l1 * a1 + rs1;

#pragma unroll
        for (int df = 0; df < 8; df++) {
            oacc[df][0] *= a0; oacc[df][1] *= a0;
            oacc[df][2] *= a1; oacc[df][3] *= a1;
        }

        // ---- O += P V  (single fp16 mma) ----
#pragma unroll
        for (int t = 0; t < 4; t++) {
            uint32_t af[4];
            af[0] = packf16x2(sacc[2 * t][0],     sacc[2 * t][1]);
            af[1] = packf16x2(sacc[2 * t][2],     sacc[2 * t][3]);
            af[2] = packf16x2(sacc[2 * t + 1][0], sacc[2 * t + 1][1]);
            af[3] = packf16x2(sacc[2 * t + 1][2], sacc[2 * t + 1][3]);
            const int rpb = t * 8 + c;
#pragma unroll
            for (int df = 0; df < 8; df++) {
                const uint32_t* vh = &sV[rpb * VP + df * 8 + g];
                uint32_t bfr[2];
                bfr[0] = vh[0];
                bfr[1] = vh[4 * VP];
                mma_f16(oacc[df], af, bfr);
            }
        }
    }

    // ---- epilogue: finish l reduction, normalize, store ----
    l0 += __shfl_xor_sync(0xffffffffu, l0, 1);
    l0 += __shfl_xor_sync(0xffffffffu, l0, 2);
    l1 += __shfl_xor_sync(0xffffffffu, l1, 1);
    l1 += __shfl_xor_sync(0xffffffffu, l1, 2);
    const float inv0 = 1.0f / l0;
    const float inv1 = 1.0f / l1;

    float* o0 = out + ((size_t)(b * Ss + r0) * Hh + h) * Dd;
    float* o1 = out + ((size_t)(b * Ss + r1) * Hh + h) * Dd;
#pragma unroll
    for (int df = 0; df < 8; df++) {
        const int dc = df * 8 + 2 * c;
        float2 w0, w1;
        w0.x = oacc[df][0] * inv0; w0.y = oacc[df][1] * inv0;
        w1.x = oacc[df][2] * inv1; w1.y = oacc[df][3] * inv1;
        *(float2*)(o0 + dc) = w0;
        *(float2*)(o1 + dc) = w1;
    }
}

} // namespace

extern "C" void kernel_launch(void* const* d_in, const int* in_sizes, int n_in,
                              void* d_out, int out_size)
{
    const float* q    = (const float*)d_in[0];
    const float* k    = (const float*)d_in[1];
    const float* v    = (const float*)d_in[2];
    const float* bias = (const float*)d_in[3];
    float* out        = (float*)d_out;

    const dim3 grid(Bb * Hh * (Ss / BM));  // 2048 CTAs, batch fastest-varying
    fa_kernel<<<grid, 128>>>(q, k, v, bias, out);
}

// round 7
// speedup vs baseline: 1.8645x; 1.2528x over previous
#include <cuda_runtime.h>
#include <cuda_bf16.h>
#include <stdint.h>

namespace {

constexpr int Bb = 4, Ss = 2048, Hh = 16, Dd = 64;
constexpr int BM = 64, BN = 64;
constexpr int KP = 36;            // u32 per sK row (f16x2 words): frag bank = 4g+c, conflict-free
constexpr int VP = 72;            // u32 per sV row-pair: frag bank = 8c+g, conflict-free
constexpr float SCALE = 0.125f;   // 1/sqrt(64)
constexpr float NEGINF = -1e30f;

// pack two floats -> f16x2 (lower half = lo arg, upper half = hi arg)
__device__ __forceinline__ uint32_t packf16x2(float lo, float hi) {
    uint32_t r;
    asm("cvt.rn.f16x2.f32 %0, %1, %2;" : "=r"(r) : "f"(hi), "f"(lo));
    return r;
}

__device__ __forceinline__ void mma_f16(float c[4], const uint32_t a[4], const uint32_t b[2]) {
    asm volatile(
        "mma.sync.aligned.m16n8k16.row.col.f32.f16.f16.f32 "
        "{%0,%1,%2,%3}, {%4,%5,%6,%7}, {%8,%9}, {%0,%1,%2,%3};"
        : "+f"(c[0]), "+f"(c[1]), "+f"(c[2]), "+f"(c[3])
        : "r"(a[0]), "r"(a[1]), "r"(a[2]), "r"(a[3]), "r"(b[0]), "r"(b[1]));
}

__global__ void __launch_bounds__(128, 3)
fa_kernel(const float* __restrict__ q, const float* __restrict__ k,
          const float* __restrict__ v, const float* __restrict__ bias,
          float* __restrict__ out)
{
    __shared__ __align__(16) uint32_t sK[BN * KP];       // K tile, f16x2 d-pairs, [n][d/2]
    __shared__ __align__(16) uint32_t sV[(BN/2) * VP];   // V tile, f16x2 seq row-pairs

    const int tid  = threadIdx.x;
    const int lane = tid & 31;
    const int wid  = tid >> 5;
    const int g    = lane >> 2;
    const int c    = lane & 3;

    // grid: batch fastest-varying (bias L2 reuse); qt reversed (longest first)
    const int idx = blockIdx.x;
    const int b   = idx & 3;
    const int h   = (idx >> 2) & 15;
    const int qt  = (Ss / BM - 1) - (idx >> 6);
    const int qrow = qt * BM;

    const int r0 = qrow + wid * 16 + g;
    const int r1 = r0 + 8;

    // ---- Q fragments (f16x2), loaded once: qa[ks][4], ks = k16 step ----
    const float* q0 = q + ((size_t)(b * Ss + r0) * Hh + h) * Dd;
    const float* q1 = q + ((size_t)(b * Ss + r1) * Hh + h) * Dd;
    uint32_t qa[4][4];
#pragma unroll
    for (int ks = 0; ks < 4; ks++) {
        const int d0 = ks * 16 + 2 * c;
        const float2 a00 = *(const float2*)(q0 + d0);
        const float2 a01 = *(const float2*)(q1 + d0);
        const float2 a10 = *(const float2*)(q0 + d0 + 8);
        const float2 a11 = *(const float2*)(q1 + d0 + 8);
        qa[ks][0] = packf16x2(a00.x, a00.y);
        qa[ks][1] = packf16x2(a01.x, a01.y);
        qa[ks][2] = packf16x2(a10.x, a10.y);
        qa[ks][3] = packf16x2(a11.x, a11.y);
    }

    float oacc[8][4];
#pragma unroll
    for (int i = 0; i < 8; i++) {
        oacc[i][0] = 0.f; oacc[i][1] = 0.f; oacc[i][2] = 0.f; oacc[i][3] = 0.f;
    }
    float m0 = NEGINF, m1 = NEGINF, l0 = 0.f, l1 = 0.f;

    const float* biasr0 = bias + ((size_t)h * Ss + r0) * Ss;
    const float* biasr1 = bias + ((size_t)h * Ss + r1) * Ss;

    for (int j = 0; j <= qt; j++) {
        __syncthreads();
        const size_t base = ((size_t)(b * Ss + j * BN) * Hh + h) * Dd;

        // ---- K tile: fp32 -> f16x2 d-pairs -> smem ----
#pragma unroll
        for (int it = 0; it < 8; it++) {
            const int t  = it * 128 + tid;
            const int n  = t >> 4;
            const int d4 = (t & 15) << 2;
            const float4 kv = *(const float4*)(k + base + (size_t)n * (Hh * Dd) + d4);
            uint2 kt;
            kt.x = packf16x2(kv.x, kv.y);
            kt.y = packf16x2(kv.z, kv.w);
            *(uint2*)(&sK[n * KP + (d4 >> 1)]) = kt;
        }
        // ---- V tile: fp32 seq row-pairs -> f16x2 -> smem ----
#pragma unroll
        for (int it = 0; it < 4; it++) {
            const int t  = it * 128 + tid;
            const int rp = t >> 4;
            const int d4 = (t & 15) << 2;
            const float* vb = v + base + (size_t)(2 * rp) * (Hh * Dd) + d4;
            const float4 v0 = *(const float4*)(vb);
            const float4 v1 = *(const float4*)(vb + Hh * Dd);
            uint4 hi;
            hi.x = packf16x2(v0.x, v1.x);
            hi.y = packf16x2(v0.y, v1.y);
            hi.z = packf16x2(v0.z, v1.z);
            hi.w = packf16x2(v0.w, v1.w);
            *(uint4*)(&sV[rp * VP + d4]) = hi;
        }
        __syncthreads();

        // ---- S = Q K^T (fp16 m16n8k16 mma) ----
        float sacc[8][4];
#pragma unroll
        for (int nf = 0; nf < 8; nf++) {
            sacc[nf][0] = 0.f; sacc[nf][1] = 0.f; sacc[nf][2] = 0.f; sacc[nf][3] = 0.f;
#pragma unroll
            for (int ks = 0; ks < 4; ks++) {
                const uint32_t* kp = &sK[(nf * 8 + g) * KP + ks * 8 + c];
                uint32_t bfr[2];
                bfr[0] = kp[0];
                bfr[1] = kp[4];
                mma_f16(sacc[nf], qa[ks], bfr);
            }
        }

        // ---- scale + bias + causal mask ----
        const int kcb = j * BN;
        const bool diag = (j == qt);
#pragma unroll
        for (int nf = 0; nf < 8; nf++) {
            const int kc = kcb + nf * 8 + 2 * c;
            const float2 bb0 = __ldg((const float2*)(biasr0 + kc));
            const float2 bb1 = __ldg((const float2*)(biasr1 + kc));
            sacc[nf][0] = sacc[nf][0] * SCALE + bb0.x;
            sacc[nf][1] = sacc[nf][1] * SCALE + bb0.y;
            sacc[nf][2] = sacc[nf][2] * SCALE + bb1.x;
            sacc[nf][3] = sacc[nf][3] * SCALE + bb1.y;
            if (diag) {
                if (kc     > r0) sacc[nf][0] = NEGINF;
                if (kc + 1 > r0) sacc[nf][1] = NEGINF;
                if (kc     > r1) sacc[nf][2] = NEGINF;
                if (kc + 1 > r1) sacc[nf][3] = NEGINF;
            }
        }

        // ---- online softmax ----
        float rm0 = NEGINF, rm1 = NEGINF;
#pragma unroll
        for (int nf = 0; nf < 8; nf++) {
            rm0 = fmaxf(rm0, fmaxf(sacc[nf][0], sacc[nf][1]));
            rm1 = fmaxf(rm1, fmaxf(sacc[nf][2], sacc[nf][3]));
        }
        rm0 = fmaxf(rm0, __shfl_xor_sync(0xffffffffu, rm0, 1));
        rm0 = fmaxf(rm0, __shfl_xor_sync(0xffffffffu, rm0, 2));
        rm1 = fmaxf(rm1, __shfl_xor_sync(0xffffffffu, rm1, 1));
        rm1 = fmaxf(rm1, __shfl_xor_sync(0xffffffffu, rm1, 2));

        const float nm0 = fmaxf(m0, rm0), nm1 = fmaxf(m1, rm1);
        const float a0 = __expf(m0 - nm0), a1 = __expf(m1 - nm1);
        m0 = nm0; m1 = nm1;

        float rs0 = 0.f, rs1 = 0.f;
#pragma unroll
        for (int nf = 0; nf < 8; nf++) {
            sacc[nf][0] = __expf(sacc[nf][0] - nm0);
            sacc[nf][1] = __expf(sacc[nf][1] - nm0);
            sacc[nf][2] = __expf(sacc[nf][2] - nm1);
            sacc[nf][3] = __expf(sacc[nf][3] - nm1);
            rs0 += sacc[nf][0] + sacc[nf][1];
            rs1 += sacc[nf][2] + sacc[nf][3];
        }
        l0 = l0 * a0 + rs0;   // quad reduction deferred to epilogue
        l1 = l1 * a1 + rs1;

#pragma unroll
        for (int df = 0; df < 8; df++) {
            oacc[df][0] *= a0; oacc[df][1] *= a0;
            oacc[df][2] *= a1; oacc[df][3] *= a1;
        }

        // ---- O += P V  (fp16 mma) ----
#pragma unroll
        for (int t = 0; t < 4; t++) {
            uint32_t af[4];
            af[0] = packf16x2(sacc[2 * t][0],     sacc[2 * t][1]);
            af[1] = packf16x2(sacc[2 * t][2],     sacc[2 * t][3]);
            af[2] = packf16x2(sacc[2 * t + 1][0], sacc[2 * t + 1][1]);
            af[3] = packf16x2(sacc[2 * t + 1][2], sacc[2 * t + 1][3]);
            const int rpb = t * 8 + c;
#pragma unroll
            for (int df = 0; df < 8; df++) {
                const uint32_t* vh = &sV[rpb * VP + df * 8 + g];
                uint32_t bfr[2];
                bfr[0] = vh[0];
                bfr[1] = vh[4 * VP];
                mma_f16(oacc[df], af, bfr);
            }
        }
    }

    // ---- epilogue: finish l reduction, normalize, store ----
    l0 += __shfl_xor_sync(0xffffffffu, l0, 1);
    l0 += __shfl_xor_sync(0xffffffffu, l0, 2);
    l1 += __shfl_xor_sync(0xffffffffu, l1, 1);
    l1 += __shfl_xor_sync(0xffffffffu, l1, 2);
    const float inv0 = 1.0f / l0;
    const float inv1 = 1.0f / l1;

    float* o0 = out + ((size_t)(b * Ss + r0) * Hh + h) * Dd;
    float* o1 = out + ((size_t)(b * Ss + r1) * Hh + h) * Dd;
#pragma unroll
    for (int df = 0; df < 8; df++) {
        const int dc = df * 8 + 2 * c;
        float2 w0, w1;
        w0.x = oacc[df][0] * inv0; w0.y = oacc[df][1] * inv0;
        w1.x = oacc[df][2] * inv1; w1.y = oacc[df][3] * inv1;
        *(float2*)(o0 + dc) = w0;
        *(float2*)(o1 + dc) = w1;
    }
}

} // namespace

extern "C" void kernel_launch(void* const* d_in, const int* in_sizes, int n_in,
                              void* d_out, int out_size)
{
    const float* q    = (const float*)d_in[0];
    const float* k    = (const float*)d_in[1];
    const float* v    = (const float*)d_in[2];
    const float* bias = (const float*)d_in[3];
    float* out        = (float*)d_out;

    const dim3 grid(Bb * Hh * (Ss / BM));  // 2048 CTAs, batch fastest-varying
    fa_kernel<<<grid, 128>>>(q, k, v, bias, out);
}